// round 5
// baseline (speedup 1.0000x reference)
#include <cuda_runtime.h>
#include <cuda_bf16.h>

// LatentMap, warp-cooperative two-phase scheme.
// R5: 64 queries per warp; phase 1 runs TWO independent scalar chains per
// lane (queries qbase+l and qbase+32+l, interleaved for 2x MLP in the
// latency-dominated scattered-gather phase). Phase 2 sweeps 64 queries,
// 4 per iteration (lane -> query sub = lane>>3, feature quad = (lane&7)*4):
// 2 LDS.128, 4 perfectly-coalesced LDG.128 gathers, 1 STG.128 (512B), FFMA.

#define IMG 1024
#define EMB 32
#define WARPS_PER_BLOCK 8
#define QUERIES_PER_WARP 64

__global__ void __launch_bounds__(WARPS_PER_BLOCK * 32) latent_map_kernel(
    const float2* __restrict__ position,      // [N_Q]
    const float2* __restrict__ positions,     // [N_PTS]
    const int4*   __restrict__ neighbor_map,  // [IMG*IMG]
    const float*  __restrict__ embeddings,    // [N_PTS, EMB]
    const float*  __restrict__ harmonics,     // [EMB]
    float*        __restrict__ out,           // [N_Q, EMB]
    int n_q)
{
    __shared__ int4   s_nb[WARPS_PER_BLOCK][QUERIES_PER_WARP];
    __shared__ float4 s_w [WARPS_PER_BLOCK][QUERIES_PER_WARP];

    const int warp = threadIdx.x >> 5;
    const int lane = threadIdx.x & 31;
    const int qbase = (blockIdx.x * WARPS_PER_BLOCK + warp) * QUERIES_PER_WARP;

    // ---- Phase 1: two independent per-query chains per lane ----
    {
        const int qa = qbase + lane;
        const int qb = qbase + 32 + lane;
        const bool va = qa < n_q;
        const bool vb = qb < n_q;

        // Interleave the two chains so both gather sequences are in flight.
        float2 pa, pb;
        if (va) pa = position[qa];
        if (vb) pb = position[qb];

        int ixa = 0, iya = 0, ixb = 0, iyb = 0;
        if (va) { ixa = (int)floorf(pa.x); iya = (int)floorf(pa.y); }
        if (vb) { ixb = (int)floorf(pb.x); iyb = (int)floorf(pb.y); }

        int4 nba, nbb;
        if (va) nba = neighbor_map[ixa * IMG + iya];
        if (vb) nbb = neighbor_map[ixb * IMG + iyb];

        float2 a0, a1, a2, a3, b0, b1, b2, b3;
        if (va) { a0 = positions[nba.x]; a1 = positions[nba.y];
                  a2 = positions[nba.z]; a3 = positions[nba.w]; }
        if (vb) { b0 = positions[nbb.x]; b1 = positions[nbb.y];
                  b2 = positions[nbb.z]; b3 = positions[nbb.w]; }

        if (va) {
            const float fx = (float)ixa, fy = (float)iya;
            float dx, dy;
            dx = a0.x - fx; dy = a0.y - fy; const float d0 = sqrtf(dx*dx + dy*dy);
            dx = a1.x - fx; dy = a1.y - fy; const float d1 = sqrtf(dx*dx + dy*dy);
            dx = a2.x - fx; dy = a2.y - fy; const float d2 = sqrtf(dx*dx + dy*dy);
            dx = a3.x - fx; dy = a3.y - fy; const float d3 = sqrtf(dx*dx + dy*dy);
            const float rs = 1.0f / (d0 + d1 + d2 + d3 + 1e-8f);
            float4 w;
            w.x = 1.0f - d0 * rs; w.y = 1.0f - d1 * rs;
            w.z = 1.0f - d2 * rs; w.w = 1.0f - d3 * rs;
            s_nb[warp][lane] = nba;
            s_w [warp][lane] = w;
        }
        if (vb) {
            const float fx = (float)ixb, fy = (float)iyb;
            float dx, dy;
            dx = b0.x - fx; dy = b0.y - fy; const float d0 = sqrtf(dx*dx + dy*dy);
            dx = b1.x - fx; dy = b1.y - fy; const float d1 = sqrtf(dx*dx + dy*dy);
            dx = b2.x - fx; dy = b2.y - fy; const float d2 = sqrtf(dx*dx + dy*dy);
            dx = b3.x - fx; dy = b3.y - fy; const float d3 = sqrtf(dx*dx + dy*dy);
            const float rs = 1.0f / (d0 + d1 + d2 + d3 + 1e-8f);
            float4 w;
            w.x = 1.0f - d0 * rs; w.y = 1.0f - d1 * rs;
            w.z = 1.0f - d2 * rs; w.w = 1.0f - d3 * rs;
            s_nb[warp][32 + lane] = nbb;
            s_w [warp][32 + lane] = w;
        }
    }
    __syncwarp();

    // ---- Phase 2: 4 queries per iteration; lane -> (query sub, feature quad)
    const int sub = lane >> 3;        // 0..3
    const int fq  = (lane & 7) * 4;   // 0,4,...,28

    const float4 h4 = *(const float4*)&harmonics[fq];

    #pragma unroll 4
    for (int i = 0; i < QUERIES_PER_WARP; i += 4) {
        const int q = qbase + i + sub;
        if (q < n_q) {
            const int4   nb = s_nb[warp][i + sub];  // LDS.128
            const float4 w  = s_w [warp][i + sub];  // LDS.128

            const float4 e0 = *(const float4*)&embeddings[(long)nb.x * EMB + fq];
            const float4 e1 = *(const float4*)&embeddings[(long)nb.y * EMB + fq];
            const float4 e2 = *(const float4*)&embeddings[(long)nb.z * EMB + fq];
            const float4 e3 = *(const float4*)&embeddings[(long)nb.w * EMB + fq];

            float4 acc;
            acc.x = w.x * e0.x + w.y * e1.x + w.z * e2.x + w.w * e3.x;
            acc.y = w.x * e0.y + w.y * e1.y + w.z * e2.y + w.w * e3.y;
            acc.z = w.x * e0.z + w.y * e1.z + w.z * e2.z + w.w * e3.z;
            acc.w = w.x * e0.w + w.y * e1.w + w.z * e2.w + w.w * e3.w;

            acc.x *= h4.x; acc.y *= h4.y; acc.z *= h4.z; acc.w *= h4.w;

            *(float4*)&out[(long)q * EMB + fq] = acc;
        }
    }
}

extern "C" void kernel_launch(void* const* d_in, const int* in_sizes, int n_in,
                              void* d_out, int out_size)
{
    const float2* position     = (const float2*)d_in[0];
    const float2* positions    = (const float2*)d_in[1];
    const int4*   neighbor_map = (const int4*)d_in[2];
    const float*  embeddings   = (const float*)d_in[3];
    const float*  harmonics    = (const float*)d_in[4];
    float*        out          = (float*)d_out;

    const int n_q = in_sizes[0] / 2;
    const int queries_per_block = WARPS_PER_BLOCK * QUERIES_PER_WARP; // 512
    const int grid = (n_q + queries_per_block - 1) / queries_per_block;
    latent_map_kernel<<<grid, WARPS_PER_BLOCK * 32>>>(
        position, positions, neighbor_map, embeddings, harmonics, out, n_q);
}

// round 6
// speedup vs baseline: 1.0578x; 1.0578x over previous
#include <cuda_runtime.h>
#include <cuda_bf16.h>

// LatentMap, warp-cooperative two-phase scheme (R4 structure, R6 tuning).
//
// Phase 1: lane l computes per-query scalars (neighbor indices + normalized
//          inverse-distance weights) for query qbase + l, once, -> smem.
// Phase 2: warp sweeps its 32 queries 4 at a time; lane -> (query sub =
//          lane>>3, feature quad = (lane&7)*4): 2 LDS.128, 4 coalesced
//          LDG.128 gathers, 1 STG.128 spanning 512B, ~20 FFMA.
//
// R6: __launch_bounds__(256, 8) to reach 8 blocks/SM (64 warps theoretical;
// more warps -> better scatter-latency hiding -> higher L1 utilization),
// and a uniform fast path with no per-iteration bounds checks (N_Q divides
// the block tile exactly).

#define IMG 1024
#define EMB 32
#define WARPS_PER_BLOCK 8
#define QUERIES_PER_WARP 32

__global__ void __launch_bounds__(WARPS_PER_BLOCK * 32, 8) latent_map_kernel(
    const float2* __restrict__ position,      // [N_Q]
    const float2* __restrict__ positions,     // [N_PTS]
    const int4*   __restrict__ neighbor_map,  // [IMG*IMG]
    const float*  __restrict__ embeddings,    // [N_PTS, EMB]
    const float*  __restrict__ harmonics,     // [EMB]
    float*        __restrict__ out,           // [N_Q, EMB]
    int n_q)
{
    __shared__ int4   s_nb[WARPS_PER_BLOCK][QUERIES_PER_WARP];
    __shared__ float4 s_w [WARPS_PER_BLOCK][QUERIES_PER_WARP];

    const int warp = threadIdx.x >> 5;
    const int lane = threadIdx.x & 31;
    const int qbase = (blockIdx.x * WARPS_PER_BLOCK + warp) * QUERIES_PER_WARP;

    // Uniform per-warp test: does this warp own a full 32-query tile?
    const bool full_tile = (qbase + QUERIES_PER_WARP) <= n_q;

    // ---- Phase 1: one query per lane, scalar work done exactly once ----
    {
        const int q = qbase + lane;
        if (full_tile || q < n_q) {
            const float2 p = position[q];
            const int ix = (int)floorf(p.x);
            const int iy = (int)floorf(p.y);
            const int4 nb = neighbor_map[ix * IMG + iy];

            const float2 p0 = positions[nb.x];
            const float2 p1 = positions[nb.y];
            const float2 p2 = positions[nb.z];
            const float2 p3 = positions[nb.w];

            const float fx = (float)ix, fy = (float)iy;
            float dx, dy;
            dx = p0.x - fx; dy = p0.y - fy;
            const float d0 = sqrtf(dx * dx + dy * dy);
            dx = p1.x - fx; dy = p1.y - fy;
            const float d1 = sqrtf(dx * dx + dy * dy);
            dx = p2.x - fx; dy = p2.y - fy;
            const float d2 = sqrtf(dx * dx + dy * dy);
            dx = p3.x - fx; dy = p3.y - fy;
            const float d3 = sqrtf(dx * dx + dy * dy);

            const float rs = 1.0f / (d0 + d1 + d2 + d3 + 1e-8f);
            float4 w;
            w.x = 1.0f - d0 * rs;
            w.y = 1.0f - d1 * rs;
            w.z = 1.0f - d2 * rs;
            w.w = 1.0f - d3 * rs;

            s_nb[warp][lane] = nb;
            s_w [warp][lane] = w;
        }
    }
    __syncwarp();

    // ---- Phase 2: 4 queries per iteration; lane -> (query sub, feature quad)
    const int sub = lane >> 3;        // 0..3
    const int fq  = (lane & 7) * 4;   // 0,4,...,28

    const float4 h4 = *(const float4*)&harmonics[fq];

    if (full_tile) {
        // Hot path: no per-iteration predicates.
        #pragma unroll
        for (int i = 0; i < QUERIES_PER_WARP; i += 4) {
            const int4   nb = s_nb[warp][i + sub];  // LDS.128
            const float4 w  = s_w [warp][i + sub];  // LDS.128

            const float4 e0 = __ldg((const float4*)&embeddings[(long)nb.x * EMB + fq]);
            const float4 e1 = __ldg((const float4*)&embeddings[(long)nb.y * EMB + fq]);
            const float4 e2 = __ldg((const float4*)&embeddings[(long)nb.z * EMB + fq]);
            const float4 e3 = __ldg((const float4*)&embeddings[(long)nb.w * EMB + fq]);

            float4 acc;
            acc.x = w.x * e0.x + w.y * e1.x + w.z * e2.x + w.w * e3.x;
            acc.y = w.x * e0.y + w.y * e1.y + w.z * e2.y + w.w * e3.y;
            acc.z = w.x * e0.z + w.y * e1.z + w.z * e2.z + w.w * e3.z;
            acc.w = w.x * e0.w + w.y * e1.w + w.z * e2.w + w.w * e3.w;

            acc.x *= h4.x; acc.y *= h4.y; acc.z *= h4.z; acc.w *= h4.w;

            *(float4*)&out[(long)(qbase + i + sub) * EMB + fq] = acc;
        }
    } else {
        #pragma unroll
        for (int i = 0; i < QUERIES_PER_WARP; i += 4) {
            const int q = qbase + i + sub;
            if (q < n_q) {
                const int4   nb = s_nb[warp][i + sub];
                const float4 w  = s_w [warp][i + sub];

                const float4 e0 = __ldg((const float4*)&embeddings[(long)nb.x * EMB + fq]);
                const float4 e1 = __ldg((const float4*)&embeddings[(long)nb.y * EMB + fq]);
                const float4 e2 = __ldg((const float4*)&embeddings[(long)nb.z * EMB + fq]);
                const float4 e3 = __ldg((const float4*)&embeddings[(long)nb.w * EMB + fq]);

                float4 acc;
                acc.x = w.x * e0.x + w.y * e1.x + w.z * e2.x + w.w * e3.x;
                acc.y = w.x * e0.y + w.y * e1.y + w.z * e2.y + w.w * e3.y;
                acc.z = w.x * e0.z + w.y * e1.z + w.z * e2.z + w.w * e3.z;
                acc.w = w.x * e0.w + w.y * e1.w + w.z * e2.w + w.w * e3.w;

                acc.x *= h4.x; acc.y *= h4.y; acc.z *= h4.z; acc.w *= h4.w;

                *(float4*)&out[(long)q * EMB + fq] = acc;
            }
        }
    }
}

extern "C" void kernel_launch(void* const* d_in, const int* in_sizes, int n_in,
                              void* d_out, int out_size)
{
    const float2* position     = (const float2*)d_in[0];
    const float2* positions    = (const float2*)d_in[1];
    const int4*   neighbor_map = (const int4*)d_in[2];
    const float*  embeddings   = (const float*)d_in[3];
    const float*  harmonics    = (const float*)d_in[4];
    float*        out          = (float*)d_out;

    const int n_q = in_sizes[0] / 2;
    const int queries_per_block = WARPS_PER_BLOCK * QUERIES_PER_WARP; // 256
    const int grid = (n_q + queries_per_block - 1) / queries_per_block;
    latent_map_kernel<<<grid, WARPS_PER_BLOCK * 32>>>(
        position, positions, neighbor_map, embeddings, harmonics, out, n_q);
}